// round 14
// baseline (speedup 1.0000x reference)
#include <cuda_runtime.h>
#include <cuda_fp16.h>
#include <math.h>
#include <stdint.h>

// ---------------------------------------------------------------------------
// Problem constants
// ---------------------------------------------------------------------------
#define P_TOT   65536            // B*H*W positions (windowed layout)
#define KDIM    512
#define E_QKV   1536
#define HEADS   16
#define L_WIN   64
#define NWIN    1024

// ---------------------------------------------------------------------------
// Scratch (static device globals: allocation-free)
// ---------------------------------------------------------------------------
__device__ __half g_xh [(size_t)P_TOT * KDIM];          // LN'd windowed input, [p][d] fp16
__device__ __half g_qkv[(size_t)P_TOT * E_QKV];         // qkv projection, [p][e] fp16
__device__ __half g_ah [(size_t)P_TOT * KDIM];          // attention out, [p][d] fp16
__device__ __half g_wq [E_QKV * KDIM];                  // weights fp16
__device__ __half g_wo [KDIM * KDIM];
__device__ float g_cos[L_WIN * 16];
__device__ float g_sin[L_WIN * 16];

// ---------------------------------------------------------------------------
// Helpers
// ---------------------------------------------------------------------------
__device__ __forceinline__ uint32_t smem_u32(const void* p) {
    uint32_t a;
    asm("{ .reg .u64 t; cvta.to.shared.u64 t, %1; cvt.u32.u64 %0, t; }" : "=r"(a) : "l"(p));
    return a;
}

__device__ __forceinline__ void cp16(uint32_t dst, const void* src) {
    asm volatile("cp.async.cg.shared.global [%0], [%1], 16;" :: "r"(dst), "l"(src));
}
__device__ __forceinline__ void cp_commit() {
    asm volatile("cp.async.commit_group;" ::: "memory");
}
template <int N>
__device__ __forceinline__ void cp_wait() {
    asm volatile("cp.async.wait_group %0;" :: "n"(N) : "memory");
}

__device__ __forceinline__ void ldm_x4(uint32_t* r, uint32_t addr) {
    asm volatile("ldmatrix.sync.aligned.m8n8.x4.shared.b16 {%0,%1,%2,%3}, [%4];"
                 : "=r"(r[0]), "=r"(r[1]), "=r"(r[2]), "=r"(r[3]) : "r"(addr));
}

__device__ __forceinline__ void ldm_x4_trans(uint32_t* r, uint32_t addr) {
    asm volatile("ldmatrix.sync.aligned.m8n8.x4.trans.shared.b16 {%0,%1,%2,%3}, [%4];"
                 : "=r"(r[0]), "=r"(r[1]), "=r"(r[2]), "=r"(r[3]) : "r"(addr));
}

__device__ __forceinline__ void mma_f16(float* c, const uint32_t* a, const uint32_t* b) {
    asm volatile(
        "mma.sync.aligned.m16n8k16.row.col.f32.f16.f16.f32 "
        "{%0,%1,%2,%3}, {%4,%5,%6,%7}, {%8,%9}, {%0,%1,%2,%3};"
        : "+f"(c[0]), "+f"(c[1]), "+f"(c[2]), "+f"(c[3])
        : "r"(a[0]), "r"(a[1]), "r"(a[2]), "r"(a[3]), "r"(b[0]), "r"(b[1]));
}

// load 32 consecutive halves -> fp32 regs
__device__ __forceinline__ void load32h(float* dst, const __half* src) {
    __half2 t[16];
    *(uint4*)(t)      = *(const uint4*)(src);
    *(uint4*)(t + 4)  = *(const uint4*)(src + 8);
    *(uint4*)(t + 8)  = *(const uint4*)(src + 16);
    *(uint4*)(t + 12) = *(const uint4*)(src + 24);
    #pragma unroll
    for (int d = 0; d < 16; d++) {
        float2 f = __half22float2(t[d]);
        dst[2 * d] = f.x; dst[2 * d + 1] = f.y;
    }
}

__device__ __forceinline__ uint32_t packh2(float a, float b) {
    __half2 h = __floats2half2_rn(a, b);
    return *(uint32_t*)&h;
}

// ---------------------------------------------------------------------------
// RoPE table init
// ---------------------------------------------------------------------------
__global__ void rope_init_kernel() {
    int idx = threadIdx.x;
    for (; idx < L_WIN * 16; idx += blockDim.x) {
        int l = idx >> 4;
        int q = idx & 15;
        int i = l >> 3;
        int j = l & 7;
        float pos, e;
        if (q < 8) { pos = (float)i; e = (float)q; }
        else       { pos = (float)j; e = (float)(q - 8); }
        float freq  = powf(10000.0f, -e / 8.0f);
        float theta = pos * freq;
        g_cos[idx] = cosf(theta);
        g_sin[idx] = sinf(theta);
    }
}

// ---------------------------------------------------------------------------
// fp32 -> fp16 weight conversion
// ---------------------------------------------------------------------------
__global__ void convw_kernel(const float* __restrict__ w,
                             __half* __restrict__ hi, int n) {
    int i = blockIdx.x * 256 + threadIdx.x;
    if (i < n) hi[i] = __float2half_rn(w[i]);
}

// ---------------------------------------------------------------------------
// LayerNorm + roll(-4,-4) + window partition -> x fp16 in [p][d] layout.
// x slice cached in smem as fp16 (33KB -> 5 CTAs/SM, no spill); LN applied
// in the output stage directly from the cache. mean/var from fp32 values.
// ---------------------------------------------------------------------------
#define XSP   520                                   // halves pitch (1040B, 16B-aligned)
#define SM_LN (32 * XSP * 2 + 2 * 512 * 4)          // 33280 + 4096 = 37376

__global__ void __launch_bounds__(256) ln_window_kernel(
    const float* __restrict__ x,
    const float* __restrict__ ln_g,
    const float* __restrict__ ln_b)
{
    extern __shared__ __align__(16) char smraw[];
    __half* xs   = (__half*)smraw;                   // [32][XSP]
    float*  sh_g = (float*)(smraw + 32 * XSP * 2);   // [512]
    float*  sh_b = sh_g + 512;                       // [512]
    __shared__ float sh_s[8][32], sh_s2[8][32];
    __shared__ float sh_m[32], sh_r[32];
    __shared__ int   sh_p[32];

    int blk = blockIdx.x;
    int w0  = (blk & 3) * 32;
    int h   = (blk >> 2) & 127;
    int bb  = blk >> 9;

    int px  = threadIdx.x & 31;
    int grp = threadIdx.x >> 5;
    int w   = w0 + px;

    for (int d = threadIdx.x; d < 512; d += 256) {
        sh_g[d] = ln_g[d];
        sh_b[d] = ln_b[d];
    }

    size_t base = (size_t)bb * (512u * 16384u) + (size_t)h * 128 + w;

    float s = 0.f, s2 = 0.f;
    #pragma unroll 8
    for (int i = 0; i < 64; i++) {
        int d = grp + 8 * i;
        float v = x[base + (size_t)d * 16384];
        xs[px * XSP + d] = __float2half_rn(v);
        s += v; s2 += v * v;
    }

    sh_s[grp][px] = s; sh_s2[grp][px] = s2;
    if (grp == 0) {
        int hs  = (h - 4) & 127;
        int ws  = (w - 4) & 127;
        int wdx = bb * 256 + (hs >> 3) * 16 + (ws >> 3);
        sh_p[px] = wdx * 64 + (hs & 7) * 8 + (ws & 7);
    }
    __syncthreads();
    if (threadIdx.x < 32) {
        float ts = 0.f, ts2 = 0.f;
        #pragma unroll
        for (int g2 = 0; g2 < 8; g2++) { ts += sh_s[g2][threadIdx.x]; ts2 += sh_s2[g2][threadIdx.x]; }
        float mean = ts * (1.0f / 512.0f);
        float var  = ts2 * (1.0f / 512.0f) - mean * mean;
        sh_m[threadIdx.x] = mean;
        sh_r[threadIdx.x] = rsqrtf(var + 1e-5f);
    }
    __syncthreads();

    // output: thread (pl, jj) -> position pl, channels [jj*64, jj*64+64)
    int pl = threadIdx.x >> 3;
    int jj = threadIdx.x & 7;
    float mean = sh_m[pl], r = sh_r[pl];
    size_t dst = (size_t)sh_p[pl] * 512 + jj * 64;
    const __half2* src = (const __half2*)(xs + pl * XSP + jj * 64);

    #pragma unroll
    for (int q = 0; q < 8; q++) {
        __half2 hin[4];
        *(uint4*)hin = *(const uint4*)(src + q * 4);
        __half2 hout[4];
        #pragma unroll
        for (int t = 0; t < 4; t++) {
            int d = jj * 64 + q * 8 + 2 * t;
            float2 f = __half22float2(hin[t]);
            float a  = (f.x - mean) * r * sh_g[d]     + sh_b[d];
            float b2 = (f.y - mean) * r * sh_g[d + 1] + sh_b[d + 1];
            hout[t] = __floats2half2_rn(a, b2);
        }
        *(uint4*)(g_xh + dst + q * 8) = *(uint4*)hout;
    }
}

// ---------------------------------------------------------------------------
// HMMA fp16 single-pass GEMM: C = W * Act^T.
// CTA tile 128x128, BK=32, 8 warps (2x4), warp tile 64x32,
// 4-stage cp.async, ONE barrier per chunk.
// MODE 0: smem-transposed -> C[p][e] fp16. MODE 1: +bias, scatter fp32.
// ---------------------------------------------------------------------------
#define ROWB     80
#define OFF_A    0
#define OFF_B    (128 * ROWB)              // 10240
#define STAGE_SZ (2 * 128 * ROWB)          // 20480
#define SM_GEMM  (4 * STAGE_SZ)            // 81920

template <int MODE>
__global__ void __launch_bounds__(256) gemm_hmma(
    const __half* __restrict__ A,          // weights [M][512]
    const __half* __restrict__ B,          // activations [65536][512]
    void* __restrict__ Cv, const float* __restrict__ bias, int EW)
{
    extern __shared__ __align__(128) char sm[];
    uint32_t smb = smem_u32(sm);

    const int tid  = threadIdx.x;
    const int wid  = tid >> 5;
    const int lane = tid & 31;
    const int bm   = blockIdx.x * 128;
    const int bn   = blockIdx.y * 128;
    const int wm   = (wid >> 2) * 64;
    const int wn   = (wid & 3) * 32;

    const int lrow = tid >> 2;           // 0..63
    const int lch  = (tid & 3) * 16;     // 0/16/32/48

    const char* pA = (const char*)A + (size_t)(bm + lrow) * 1024 + lch;
    const char* pB = (const char*)B + (size_t)(bn + lrow) * 1024 + lch;

    float acc[4][4][4];
    #pragma unroll
    for (int i = 0; i < 4; i++)
        #pragma unroll
        for (int j = 0; j < 4; j++)
            #pragma unroll
            for (int q = 0; q < 4; q++) acc[i][j][q] = 0.f;

    const int l7  = lane & 7;
    const int sel = lane >> 3;
    const int a_r = (sel & 1) * 8 + l7;
    const int a_k = (sel >> 1) * 16;
    const int b_r = (sel >> 1) * 8 + l7;
    const int b_k = (sel & 1) * 16;

    auto load_stage = [&](int ch, int st) {
        const size_t gk = (size_t)ch * 64;
        uint32_t sb = smb + st * STAGE_SZ;
        #pragma unroll
        for (int r = 0; r < 2; r++) {
            int row = lrow + r * 64;
            uint32_t dof = row * ROWB + lch;
            size_t   sof = gk + (size_t)r * 64 * 1024;
            cp16(sb + OFF_A + dof, pA + sof);
            cp16(sb + OFF_B + dof, pB + sof);
        }
        cp_commit();
    };

    load_stage(0, 0);
    load_stage(1, 1);

    #pragma unroll 1
    for (int ch = 0; ch < 16; ch++) {
        if (ch < 14) {
            load_stage(ch + 2, (ch + 2) & 3);
            cp_wait<2>();
        } else if (ch == 14) {
            cp_wait<1>();
        } else {
            cp_wait<0>();
        }
        __syncthreads();   // single barrier per chunk (4-stage, depth-2 prefetch)

        uint32_t sb = smb + (ch & 3) * STAGE_SZ;
        uint32_t aA = sb + OFF_A + (wm + a_r) * ROWB + a_k;
        uint32_t aB = sb + OFF_B + (wn + b_r) * ROWB + b_k;

        #pragma unroll
        for (int ks = 0; ks < 2; ks++) {
            int kb = ks * 32;
            uint32_t af[4][4], bf[4][2];
            #pragma unroll
            for (int mt = 0; mt < 4; mt++)
                ldm_x4(af[mt], aA + mt * (16 * ROWB) + kb);
            #pragma unroll
            for (int np = 0; np < 2; np++) {
                uint32_t t4[4];
                ldm_x4(t4, aB + np * (16 * ROWB) + kb);
                bf[2 * np][0] = t4[0]; bf[2 * np][1] = t4[1];
                bf[2 * np + 1][0] = t4[2]; bf[2 * np + 1][1] = t4[3];
            }
            #pragma unroll
            for (int mt = 0; mt < 4; mt++)
                #pragma unroll
                for (int nt = 0; nt < 4; nt++)
                    mma_f16(acc[mt][nt], af[mt], bf[nt]);
        }
    }

    // ------------------------------ epilogue ------------------------------
    const int mrow0 = bm + wm + (lane >> 2);
    const int ncol0 = bn + wn + (lane & 3) * 2;

    if (MODE == 0) {
        __syncthreads();   // drain last-chunk reads before reusing smem
        float* smt = (float*)sm;   // [128 p][132 e]
        #pragma unroll
        for (int mt = 0; mt < 4; mt++) {
            #pragma unroll
            for (int nt = 0; nt < 4; nt++) {
                int e0  = wm + (lane >> 2) + mt * 16;
                int pl0 = wn + (lane & 3) * 2 + nt * 8;
                smt[(pl0)     * 132 + e0]     = acc[mt][nt][0];
                smt[(pl0 + 1) * 132 + e0]     = acc[mt][nt][1];
                smt[(pl0)     * 132 + e0 + 8] = acc[mt][nt][2];
                smt[(pl0 + 1) * 132 + e0 + 8] = acc[mt][nt][3];
            }
        }
        __syncthreads();
        __half* Ch = (__half*)Cv;
        int colb = (tid & 15) * 8;
        int rowb = tid >> 4;          // 0..15
        #pragma unroll
        for (int i = 0; i < 8; i++) {
            int row = rowb + i * 16;
            float4 v0 = *(float4*)&smt[row * 132 + colb];
            float4 v1 = *(float4*)&smt[row * 132 + colb + 4];
            __half2 hv[4];
            hv[0] = __floats2half2_rn(v0.x, v0.y);
            hv[1] = __floats2half2_rn(v0.z, v0.w);
            hv[2] = __floats2half2_rn(v1.x, v1.y);
            hv[3] = __floats2half2_rn(v1.z, v1.w);
            *(uint4*)(Ch + (size_t)(bn + row) * EW + bm + colb) = *(uint4*)hv;
        }
    } else {
        float* C = (float*)Cv;
        #pragma unroll
        for (int mt = 0; mt < 4; mt++) {
            float bo0 = bias[mrow0 + mt * 16];
            float bo1 = bias[mrow0 + mt * 16 + 8];
            #pragma unroll
            for (int nt = 0; nt < 4; nt++) {
                int p   = ncol0 + nt * 8;       // even; p+1 in same window row
                int wdx = p >> 6, l = p & 63;
                int bb  = wdx >> 8, rem = wdx & 255;
                int hs  = ((rem >> 4) << 3) + (l >> 3);
                int ws  = ((rem & 15) << 3) + (l & 7);
                int hh  = (hs + 4) & 127;
                int ww  = (ws + 4) & 127;
                #pragma unroll
                for (int qh = 0; qh < 2; qh++) {
                    int m = mrow0 + mt * 16 + qh * 8;
                    float bo = qh ? bo1 : bo0;
                    size_t idx = (((size_t)bb * 512 + m) << 14) + (hh << 7) + ww;
                    *(float2*)(C + idx) =
                        make_float2(acc[mt][nt][2 * qh] + bo, acc[mt][nt][2 * qh + 1] + bo);
                }
            }
        }
    }
}

// ---------------------------------------------------------------------------
// HMMA flash attention: one warp = one (window, head). Block = 4 warps.
// ---------------------------------------------------------------------------
#define AROW   80
#define TEN_SZ (64 * AROW)          // 5120 per tensor
#define WRP_SZ (3 * TEN_SZ)         // 15360 per warp
#define SM_ATT (4 * WRP_SZ)         // 61440 per block

__global__ void __launch_bounds__(128) attn_kernel() {
    extern __shared__ __align__(128) char sa[];
    int wid  = threadIdx.x >> 5;
    int lane = threadIdx.x & 31;
    int win  = blockIdx.x;
    int head = blockIdx.y * 4 + wid;
    int p0   = win * 64;

    char* Q = sa + wid * WRP_SZ;
    char* K = Q + TEN_SZ;
    char* V = K + TEN_SZ;
    uint32_t Qs = smem_u32(Q), Ks = smem_u32(K), Vs = smem_u32(V);

    const float scale = 0.17677669529663687f;   // 32^-0.5

    // fill Q/K/V rows (RoPE applied; q pre-scaled)
    #pragma unroll
    for (int it = 0; it < 2; it++) {
        int rr = lane + it * 32;
        const __half* base = g_qkv + (size_t)(p0 + rr) * E_QKV + head * 32;
        float qv[32], kv[32], vv[32];
        load32h(qv, base);
        load32h(kv, base + 512);
        load32h(vv, base + 1024);
        #pragma unroll
        for (int d = 0; d < 16; d++) {
            float c = g_cos[rr * 16 + d];
            float s = g_sin[rr * 16 + d];
            float q1 = qv[d], q2 = qv[d + 16];
            qv[d]      = (q1 * c - q2 * s) * scale;
            qv[d + 16] = (q2 * c + q1 * s) * scale;
            float k1 = kv[d], k2 = kv[d + 16];
            kv[d]      = k1 * c - k2 * s;
            kv[d + 16] = k2 * c + k1 * s;
        }
        uint4* qd = (uint4*)(Q + rr * AROW);
        uint4* kd = (uint4*)(K + rr * AROW);
        uint4* vd = (uint4*)(V + rr * AROW);
        #pragma unroll
        for (int i = 0; i < 4; i++) {
            uint4 uq, uk, uv;
            uq.x = packh2(qv[8*i+0], qv[8*i+1]); uq.y = packh2(qv[8*i+2], qv[8*i+3]);
            uq.z = packh2(qv[8*i+4], qv[8*i+5]); uq.w = packh2(qv[8*i+6], qv[8*i+7]);
            uk.x = packh2(kv[8*i+0], kv[8*i+1]); uk.y = packh2(kv[8*i+2], kv[8*i+3]);
            uk.z = packh2(kv[8*i+4], kv[8*i+5]); uk.w = packh2(kv[8*i+6], kv[8*i+7]);
            uv.x = packh2(vv[8*i+0], vv[8*i+1]); uv.y = packh2(vv[8*i+2], vv[8*i+3]);
            uv.z = packh2(vv[8*i+4], vv[8*i+5]); uv.w = packh2(vv[8*i+6], vv[8*i+7]);
            qd[i] = uq; kd[i] = uk; vd[i] = uv;
        }
    }
    __syncwarp();

    const int l7  = lane & 7;
    const int sel = lane >> 3;
    const int a_r = (sel & 1) * 8 + l7;
    const int a_k = (sel >> 1) * 16;
    const int b_r = (sel >> 1) * 8 + l7;
    const int b_k = (sel & 1) * 16;

    // Q fragments: 4 m-tiles x 2 k-tiles
    uint32_t qf[4][2][4];
    #pragma unroll
    for (int mt = 0; mt < 4; mt++)
        #pragma unroll
        for (int kk = 0; kk < 2; kk++)
            ldm_x4(qf[mt][kk], Qs + (mt * 16 + a_r) * AROW + kk * 32 + a_k);

    float oacc[4][4][4];
    #pragma unroll
    for (int i = 0; i < 4; i++)
        #pragma unroll
        for (int j = 0; j < 4; j++)
            #pragma unroll
            for (int q = 0; q < 4; q++) oacc[i][j][q] = 0.f;

    float mrow[4][2], srow[4][2];
    #pragma unroll
    for (int i = 0; i < 4; i++) { mrow[i][0] = mrow[i][1] = -1e30f; srow[i][0] = srow[i][1] = 0.f; }

    #pragma unroll 1
    for (int c0 = 0; c0 < 64; c0 += 16) {
        // K fragments for this 16-key chunk: 2 n-tiles x 2 k-tiles
        uint32_t kf[2][2][2];
        #pragma unroll
        for (int kk = 0; kk < 2; kk++) {
            uint32_t t4[4];
            ldm_x4(t4, Ks + (c0 + b_r) * AROW + kk * 32 + b_k);
            kf[0][kk][0] = t4[0]; kf[0][kk][1] = t4[1];
            kf[1][kk][0] = t4[2]; kf[1][kk][1] = t4[3];
        }

        // S chunk = Q K^T : 4 mt x 2 nt
        float sc[4][2][4];
        #pragma unroll
        for (int mt = 0; mt < 4; mt++)
            #pragma unroll
            for (int nt = 0; nt < 2; nt++) {
                #pragma unroll
                for (int q = 0; q < 4; q++) sc[mt][nt][q] = 0.f;
                mma_f16(sc[mt][nt], qf[mt][0], kf[nt][0]);
                mma_f16(sc[mt][nt], qf[mt][1], kf[nt][1]);
            }

        // softmax statistics + exp + pack P, rescale O
        uint32_t pf[4][4];
        float fr[4][2];
        #pragma unroll
        for (int mt = 0; mt < 4; mt++) {
            #pragma unroll
            for (int h2 = 0; h2 < 2; h2++) {
                float v0 = sc[mt][0][2 * h2], v1 = sc[mt][0][2 * h2 + 1];
                float v2 = sc[mt][1][2 * h2], v3 = sc[mt][1][2 * h2 + 1];
                float cm = fmaxf(fmaxf(v0, v1), fmaxf(v2, v3));
                cm = fmaxf(cm, __shfl_xor_sync(0xFFFFFFFF, cm, 1));
                cm = fmaxf(cm, __shfl_xor_sync(0xFFFFFFFF, cm, 2));
                float mn = fmaxf(mrow[mt][h2], cm);
                float f  = __expf(mrow[mt][h2] - mn);
                mrow[mt][h2] = mn;
                fr[mt][h2]   = f;
                float e0 = __expf(v0 - mn), e1 = __expf(v1 - mn);
                float e2 = __expf(v2 - mn), e3 = __expf(v3 - mn);
                float cs = e0 + e1 + e2 + e3;
                cs += __shfl_xor_sync(0xFFFFFFFF, cs, 1);
                cs += __shfl_xor_sync(0xFFFFFFFF, cs, 2);
                srow[mt][h2] = srow[mt][h2] * f + cs;
                sc[mt][0][2 * h2] = e0; sc[mt][0][2 * h2 + 1] = e1;
                sc[mt][1][2 * h2] = e2; sc[mt][1][2 * h2 + 1] = e3;
            }
            pf[mt][0] = packh2(sc[mt][0][0], sc[mt][0][1]);
            pf[mt][1] = packh2(sc[mt][0][2], sc[mt][0][3]);
            pf[mt][2] = packh2(sc[mt][1][0], sc[mt][1][1]);
            pf[mt][3] = packh2(sc[mt][1][2], sc[mt][1][3]);
        }

        // V fragments (trans): k rows = chunk keys, n = 32 head dims (4 tiles)
        uint32_t vf[4][2];
        #pragma unroll
        for (int nh = 0; nh < 2; nh++) {
            uint32_t t4[4];
            ldm_x4_trans(t4, Vs + (c0 + (sel & 1) * 8 + l7) * AROW
                               + (sel >> 1) * 16 + nh * 32);
            vf[2 * nh][0] = t4[0]; vf[2 * nh][1] = t4[1];
            vf[2 * nh + 1][0] = t4[2]; vf[2 * nh + 1][1] = t4[3];
        }

        // rescale O, then PV accumulate
        #pragma unroll
        for (int mt = 0; mt < 4; mt++)
            #pragma unroll
            for (int nd = 0; nd < 4; nd++) {
                oacc[mt][nd][0] *= fr[mt][0];
                oacc[mt][nd][1] *= fr[mt][0];
                oacc[mt][nd][2] *= fr[mt][1];
                oacc[mt][nd][3] *= fr[mt][1];
            }
        #pragma unroll
        for (int mt = 0; mt < 4; mt++)
            #pragma unroll
            for (int nd = 0; nd < 4; nd++)
                mma_f16(oacc[mt][nd], pf[mt], vf[nd]);
    }

    // normalize + write out fp16 [p][d]
    #pragma unroll
    for (int mt = 0; mt < 4; mt++) {
        float i0 = 1.f / srow[mt][0];
        float i1 = 1.f / srow[mt][1];
        int r0 = mt * 16 + (lane >> 2);
        #pragma unroll
        for (int nd = 0; nd < 4; nd++) {
            int col = nd * 8 + (lane & 3) * 2;
            __half2 h0 = __floats2half2_rn(oacc[mt][nd][0] * i0, oacc[mt][nd][1] * i0);
            __half2 h1 = __floats2half2_rn(oacc[mt][nd][2] * i1, oacc[mt][nd][3] * i1);
            *(__half2*)(g_ah + (size_t)(p0 + r0) * 512 + head * 32 + col)     = h0;
            *(__half2*)(g_ah + (size_t)(p0 + r0 + 8) * 512 + head * 32 + col) = h1;
        }
    }
}

// ---------------------------------------------------------------------------
// Launch
// ---------------------------------------------------------------------------
extern "C" void kernel_launch(void* const* d_in, const int* in_sizes, int n_in,
                              void* d_out, int out_size)
{
    const float* x     = (const float*)d_in[0];
    const float* ln_g  = (const float*)d_in[1];
    const float* ln_b  = (const float*)d_in[2];
    const float* w_qkv = (const float*)d_in[3];
    const float* w_out = (const float*)d_in[4];
    const float* b_out = (const float*)d_in[5];
    float* out = (float*)d_out;

    cudaFuncSetAttribute(gemm_hmma<0>, cudaFuncAttributeMaxDynamicSharedMemorySize, SM_GEMM);
    cudaFuncSetAttribute(gemm_hmma<1>, cudaFuncAttributeMaxDynamicSharedMemorySize, SM_GEMM);
    cudaFuncSetAttribute(attn_kernel, cudaFuncAttributeMaxDynamicSharedMemorySize, SM_ATT);
    cudaFuncSetAttribute(ln_window_kernel, cudaFuncAttributeMaxDynamicSharedMemorySize, SM_LN);

    __half *qkv, *xh, *ah, *wq, *wo;
    cudaGetSymbolAddress((void**)&qkv, g_qkv);
    cudaGetSymbolAddress((void**)&xh,  g_xh);
    cudaGetSymbolAddress((void**)&ah,  g_ah);
    cudaGetSymbolAddress((void**)&wq,  g_wq);
    cudaGetSymbolAddress((void**)&wo,  g_wo);

    rope_init_kernel<<<1, 512>>>();
    convw_kernel<<<(E_QKV * KDIM + 255) / 256, 256>>>(w_qkv, wq, E_QKV * KDIM);
    convw_kernel<<<(KDIM * KDIM + 255) / 256, 256>>>(w_out, wo, KDIM * KDIM);
    ln_window_kernel<<<2048, 256, SM_LN>>>(x, ln_g, ln_b);

    {
        dim3 grid(E_QKV / 128, P_TOT / 128);   // (12, 512), bm fastest for L2 reuse
        gemm_hmma<0><<<grid, 256, SM_GEMM>>>(wq, xh, qkv, nullptr, E_QKV);
    }

    {
        dim3 grid(NWIN, HEADS / 4);            // (1024, 4), 4 warps = 4 heads/block
        attn_kernel<<<grid, 128, SM_ATT>>>();
    }

    {
        dim3 grid(KDIM / 128, P_TOT / 128);    // (4, 512)
        gemm_hmma<1><<<grid, 256, SM_GEMM>>>(wo, ah, out, b_out, 0);
    }
}

// round 16
// speedup vs baseline: 1.0518x; 1.0518x over previous
#include <cuda_runtime.h>
#include <cuda_fp16.h>
#include <math.h>
#include <stdint.h>

// ---------------------------------------------------------------------------
// Problem constants
// ---------------------------------------------------------------------------
#define P_TOT   65536            // B*H*W positions (windowed layout)
#define KDIM    512
#define E_QKV   1536
#define HEADS   16
#define L_WIN   64
#define NWIN    1024

// ---------------------------------------------------------------------------
// Scratch (static device globals: allocation-free)
// ---------------------------------------------------------------------------
__device__ __half g_xh [(size_t)P_TOT * KDIM];          // LN'd windowed input, [p][d] fp16
__device__ __half g_qkv[(size_t)P_TOT * E_QKV];         // qkv projection, [p][e] fp16
__device__ __half g_ah [(size_t)P_TOT * KDIM];          // attention out, [p][d] fp16
__device__ __half g_wq [E_QKV * KDIM];                  // weights fp16
__device__ __half g_wo [KDIM * KDIM];
__device__ float g_cos[L_WIN * 16];
__device__ float g_sin[L_WIN * 16];

// ---------------------------------------------------------------------------
// Helpers
// ---------------------------------------------------------------------------
__device__ __forceinline__ uint32_t smem_u32(const void* p) {
    uint32_t a;
    asm("{ .reg .u64 t; cvta.to.shared.u64 t, %1; cvt.u32.u64 %0, t; }" : "=r"(a) : "l"(p));
    return a;
}

__device__ __forceinline__ void cp16(uint32_t dst, const void* src) {
    asm volatile("cp.async.cg.shared.global [%0], [%1], 16;" :: "r"(dst), "l"(src));
}
__device__ __forceinline__ void cp_commit() {
    asm volatile("cp.async.commit_group;" ::: "memory");
}
template <int N>
__device__ __forceinline__ void cp_wait() {
    asm volatile("cp.async.wait_group %0;" :: "n"(N) : "memory");
}

__device__ __forceinline__ void ldm_x4(uint32_t* r, uint32_t addr) {
    asm volatile("ldmatrix.sync.aligned.m8n8.x4.shared.b16 {%0,%1,%2,%3}, [%4];"
                 : "=r"(r[0]), "=r"(r[1]), "=r"(r[2]), "=r"(r[3]) : "r"(addr));
}

__device__ __forceinline__ void ldm_x4_trans(uint32_t* r, uint32_t addr) {
    asm volatile("ldmatrix.sync.aligned.m8n8.x4.trans.shared.b16 {%0,%1,%2,%3}, [%4];"
                 : "=r"(r[0]), "=r"(r[1]), "=r"(r[2]), "=r"(r[3]) : "r"(addr));
}

__device__ __forceinline__ void mma_f16(float* c, const uint32_t* a, const uint32_t* b) {
    asm volatile(
        "mma.sync.aligned.m16n8k16.row.col.f32.f16.f16.f32 "
        "{%0,%1,%2,%3}, {%4,%5,%6,%7}, {%8,%9}, {%0,%1,%2,%3};"
        : "+f"(c[0]), "+f"(c[1]), "+f"(c[2]), "+f"(c[3])
        : "r"(a[0]), "r"(a[1]), "r"(a[2]), "r"(a[3]), "r"(b[0]), "r"(b[1]));
}

// load 32 consecutive halves -> fp32 regs
__device__ __forceinline__ void load32h(float* dst, const __half* src) {
    __half2 t[16];
    *(uint4*)(t)      = *(const uint4*)(src);
    *(uint4*)(t + 4)  = *(const uint4*)(src + 8);
    *(uint4*)(t + 8)  = *(const uint4*)(src + 16);
    *(uint4*)(t + 12) = *(const uint4*)(src + 24);
    #pragma unroll
    for (int d = 0; d < 16; d++) {
        float2 f = __half22float2(t[d]);
        dst[2 * d] = f.x; dst[2 * d + 1] = f.y;
    }
}

__device__ __forceinline__ uint32_t packh2(float a, float b) {
    __half2 h = __floats2half2_rn(a, b);
    return *(uint32_t*)&h;
}

// ---------------------------------------------------------------------------
// RoPE table init
// ---------------------------------------------------------------------------
__global__ void rope_init_kernel() {
    int idx = threadIdx.x;
    for (; idx < L_WIN * 16; idx += blockDim.x) {
        int l = idx >> 4;
        int q = idx & 15;
        int i = l >> 3;
        int j = l & 7;
        float pos, e;
        if (q < 8) { pos = (float)i; e = (float)q; }
        else       { pos = (float)j; e = (float)(q - 8); }
        float freq  = powf(10000.0f, -e / 8.0f);
        float theta = pos * freq;
        g_cos[idx] = cosf(theta);
        g_sin[idx] = sinf(theta);
    }
}

// ---------------------------------------------------------------------------
// fp32 -> fp16 weight conversion
// ---------------------------------------------------------------------------
__global__ void convw_kernel(const float* __restrict__ w,
                             __half* __restrict__ hi, int n) {
    int i = blockIdx.x * 256 + threadIdx.x;
    if (i < n) hi[i] = __float2half_rn(w[i]);
}

// ---------------------------------------------------------------------------
// LayerNorm + roll(-4,-4) + window partition -> x fp16 in [p][d] layout.
// Round-12 structure; __launch_bounds__(256, 2) raises the reg cap to 128 so
// vals[64] stays in registers (the default heuristic spilled it to local).
// ---------------------------------------------------------------------------
__global__ void __launch_bounds__(256, 2) ln_window_kernel(
    const float* __restrict__ x,
    const float* __restrict__ ln_g,
    const float* __restrict__ ln_b)
{
    int blk = blockIdx.x;
    int w0  = (blk & 3) * 32;
    int h   = (blk >> 2) & 127;
    int bb  = blk >> 9;

    int px  = threadIdx.x & 31;
    int grp = threadIdx.x >> 5;
    int w   = w0 + px;

    __shared__ float sh_s[8][32], sh_s2[8][32];
    __shared__ float sh_m[32], sh_r[32];
    __shared__ int   sh_p[32];
    __shared__ float sh_g[512], sh_b[512];
    __shared__ float sh_t[32][132];

    for (int d = threadIdx.x; d < 512; d += 256) {
        sh_g[d] = ln_g[d];
        sh_b[d] = ln_b[d];
    }

    size_t base = (size_t)bb * (512u * 16384u) + (size_t)h * 128 + w;

    float vals[64];
    float s = 0.f, s2 = 0.f;
    #pragma unroll 8
    for (int i = 0; i < 64; i++) {
        float v = x[base + (size_t)(grp + 8 * i) * 16384];
        vals[i] = v;
        s += v; s2 += v * v;
    }

    sh_s[grp][px] = s; sh_s2[grp][px] = s2;
    if (grp == 0) {
        int hs  = (h - 4) & 127;
        int ws  = (w - 4) & 127;
        int wdx = bb * 256 + (hs >> 3) * 16 + (ws >> 3);
        sh_p[px] = wdx * 64 + (hs & 7) * 8 + (ws & 7);
    }
    __syncthreads();
    if (threadIdx.x < 32) {
        float ts = 0.f, ts2 = 0.f;
        #pragma unroll
        for (int g2 = 0; g2 < 8; g2++) { ts += sh_s[g2][threadIdx.x]; ts2 += sh_s2[g2][threadIdx.x]; }
        float mean = ts * (1.0f / 512.0f);
        float var  = ts2 * (1.0f / 512.0f) - mean * mean;
        sh_m[threadIdx.x] = mean;
        sh_r[threadIdx.x] = rsqrtf(var + 1e-5f);
    }
    __syncthreads();

    float mean = sh_m[px], r = sh_r[px];

    int pl = threadIdx.x >> 3;
    int jj = threadIdx.x & 7;

    for (int c = 0; c < 4; c++) {
        #pragma unroll
        for (int ii = 0; ii < 16; ii++) {
            int d = c * 128 + grp + 8 * ii;
            float xn = (vals[c * 16 + ii] - mean) * r * sh_g[d] + sh_b[d];
            sh_t[px][grp + 8 * ii] = xn;
        }
        __syncthreads();

        size_t dst = (size_t)sh_p[pl] * 512 + c * 128 + jj * 16;
        __half2 hv[8];
        #pragma unroll
        for (int t2 = 0; t2 < 8; t2++) {
            hv[t2] = __floats2half2_rn(sh_t[pl][jj * 16 + 2 * t2],
                                       sh_t[pl][jj * 16 + 2 * t2 + 1]);
        }
        *(uint4*)(g_xh + dst) = ((uint4*)hv)[0];
        *(uint4*)(g_xh + dst + 8) = ((uint4*)hv)[1];
        __syncthreads();
    }
}

// ---------------------------------------------------------------------------
// HMMA fp16 single-pass GEMM: C = W * Act^T.
// CTA tile 128x128, BK=32, 8 warps (2x4), warp tile 64x32,
// 4-stage cp.async, ONE barrier per chunk.
// MODE 0: smem-transposed -> C[p][e] fp16. MODE 1: +bias, scatter fp32.
// ---------------------------------------------------------------------------
#define ROWB     80
#define OFF_A    0
#define OFF_B    (128 * ROWB)              // 10240
#define STAGE_SZ (2 * 128 * ROWB)          // 20480
#define SM_GEMM  (4 * STAGE_SZ)            // 81920

template <int MODE>
__global__ void __launch_bounds__(256) gemm_hmma(
    const __half* __restrict__ A,          // weights [M][512]
    const __half* __restrict__ B,          // activations [65536][512]
    void* __restrict__ Cv, const float* __restrict__ bias, int EW)
{
    extern __shared__ __align__(128) char sm[];
    uint32_t smb = smem_u32(sm);

    const int tid  = threadIdx.x;
    const int wid  = tid >> 5;
    const int lane = tid & 31;
    const int bm   = blockIdx.x * 128;
    const int bn   = blockIdx.y * 128;
    const int wm   = (wid >> 2) * 64;
    const int wn   = (wid & 3) * 32;

    const int lrow = tid >> 2;           // 0..63
    const int lch  = (tid & 3) * 16;     // 0/16/32/48

    const char* pA = (const char*)A + (size_t)(bm + lrow) * 1024 + lch;
    const char* pB = (const char*)B + (size_t)(bn + lrow) * 1024 + lch;

    float acc[4][4][4];
    #pragma unroll
    for (int i = 0; i < 4; i++)
        #pragma unroll
        for (int j = 0; j < 4; j++)
            #pragma unroll
            for (int q = 0; q < 4; q++) acc[i][j][q] = 0.f;

    const int l7  = lane & 7;
    const int sel = lane >> 3;
    const int a_r = (sel & 1) * 8 + l7;
    const int a_k = (sel >> 1) * 16;
    const int b_r = (sel >> 1) * 8 + l7;
    const int b_k = (sel & 1) * 16;

    auto load_stage = [&](int ch, int st) {
        const size_t gk = (size_t)ch * 64;
        uint32_t sb = smb + st * STAGE_SZ;
        #pragma unroll
        for (int r = 0; r < 2; r++) {
            int row = lrow + r * 64;
            uint32_t dof = row * ROWB + lch;
            size_t   sof = gk + (size_t)r * 64 * 1024;
            cp16(sb + OFF_A + dof, pA + sof);
            cp16(sb + OFF_B + dof, pB + sof);
        }
        cp_commit();
    };

    load_stage(0, 0);
    load_stage(1, 1);

    #pragma unroll 1
    for (int ch = 0; ch < 16; ch++) {
        if (ch < 14) {
            load_stage(ch + 2, (ch + 2) & 3);
            cp_wait<2>();
        } else if (ch == 14) {
            cp_wait<1>();
        } else {
            cp_wait<0>();
        }
        __syncthreads();   // single barrier per chunk (4-stage, depth-2 prefetch)

        uint32_t sb = smb + (ch & 3) * STAGE_SZ;
        uint32_t aA = sb + OFF_A + (wm + a_r) * ROWB + a_k;
        uint32_t aB = sb + OFF_B + (wn + b_r) * ROWB + b_k;

        #pragma unroll
        for (int ks = 0; ks < 2; ks++) {
            int kb = ks * 32;
            uint32_t af[4][4], bf[4][2];
            #pragma unroll
            for (int mt = 0; mt < 4; mt++)
                ldm_x4(af[mt], aA + mt * (16 * ROWB) + kb);
            #pragma unroll
            for (int np = 0; np < 2; np++) {
                uint32_t t4[4];
                ldm_x4(t4, aB + np * (16 * ROWB) + kb);
                bf[2 * np][0] = t4[0]; bf[2 * np][1] = t4[1];
                bf[2 * np + 1][0] = t4[2]; bf[2 * np + 1][1] = t4[3];
            }
            #pragma unroll
            for (int mt = 0; mt < 4; mt++)
                #pragma unroll
                for (int nt = 0; nt < 4; nt++)
                    mma_f16(acc[mt][nt], af[mt], bf[nt]);
        }
    }

    // ------------------------------ epilogue ------------------------------
    const int mrow0 = bm + wm + (lane >> 2);
    const int ncol0 = bn + wn + (lane & 3) * 2;

    if (MODE == 0) {
        __syncthreads();   // drain last-chunk reads before reusing smem
        float* smt = (float*)sm;   // [128 p][132 e]
        #pragma unroll
        for (int mt = 0; mt < 4; mt++) {
            #pragma unroll
            for (int nt = 0; nt < 4; nt++) {
                int e0  = wm + (lane >> 2) + mt * 16;
                int pl0 = wn + (lane & 3) * 2 + nt * 8;
                smt[(pl0)     * 132 + e0]     = acc[mt][nt][0];
                smt[(pl0 + 1) * 132 + e0]     = acc[mt][nt][1];
                smt[(pl0)     * 132 + e0 + 8] = acc[mt][nt][2];
                smt[(pl0 + 1) * 132 + e0 + 8] = acc[mt][nt][3];
            }
        }
        __syncthreads();
        __half* Ch = (__half*)Cv;
        int colb = (tid & 15) * 8;
        int rowb = tid >> 4;          // 0..15
        #pragma unroll
        for (int i = 0; i < 8; i++) {
            int row = rowb + i * 16;
            float4 v0 = *(float4*)&smt[row * 132 + colb];
            float4 v1 = *(float4*)&smt[row * 132 + colb + 4];
            __half2 hv[4];
            hv[0] = __floats2half2_rn(v0.x, v0.y);
            hv[1] = __floats2half2_rn(v0.z, v0.w);
            hv[2] = __floats2half2_rn(v1.x, v1.y);
            hv[3] = __floats2half2_rn(v1.z, v1.w);
            *(uint4*)(Ch + (size_t)(bn + row) * EW + bm + colb) = *(uint4*)hv;
        }
    } else {
        float* C = (float*)Cv;
        #pragma unroll
        for (int mt = 0; mt < 4; mt++) {
            float bo0 = bias[mrow0 + mt * 16];
            float bo1 = bias[mrow0 + mt * 16 + 8];
            #pragma unroll
            for (int nt = 0; nt < 4; nt++) {
                int p   = ncol0 + nt * 8;       // even; p+1 in same window row
                int wdx = p >> 6, l = p & 63;
                int bb  = wdx >> 8, rem = wdx & 255;
                int hs  = ((rem >> 4) << 3) + (l >> 3);
                int ws  = ((rem & 15) << 3) + (l & 7);
                int hh  = (hs + 4) & 127;
                int ww  = (ws + 4) & 127;
                #pragma unroll
                for (int qh = 0; qh < 2; qh++) {
                    int m = mrow0 + mt * 16 + qh * 8;
                    float bo = qh ? bo1 : bo0;
                    size_t idx = (((size_t)bb * 512 + m) << 14) + (hh << 7) + ww;
                    *(float2*)(C + idx) =
                        make_float2(acc[mt][nt][2 * qh] + bo, acc[mt][nt][2 * qh + 1] + bo);
                }
            }
        }
    }
}

// ---------------------------------------------------------------------------
// HMMA flash attention: one warp = one (window, head). Block = 4 warps.
// ---------------------------------------------------------------------------
#define AROW   80
#define TEN_SZ (64 * AROW)          // 5120 per tensor
#define WRP_SZ (3 * TEN_SZ)         // 15360 per warp
#define SM_ATT (4 * WRP_SZ)         // 61440 per block

__global__ void __launch_bounds__(128) attn_kernel() {
    extern __shared__ __align__(128) char sa[];
    int wid  = threadIdx.x >> 5;
    int lane = threadIdx.x & 31;
    int win  = blockIdx.x;
    int head = blockIdx.y * 4 + wid;
    int p0   = win * 64;

    char* Q = sa + wid * WRP_SZ;
    char* K = Q + TEN_SZ;
    char* V = K + TEN_SZ;
    uint32_t Qs = smem_u32(Q), Ks = smem_u32(K), Vs = smem_u32(V);

    const float scale = 0.17677669529663687f;   // 32^-0.5

    // fill Q/K/V rows (RoPE applied; q pre-scaled)
    #pragma unroll
    for (int it = 0; it < 2; it++) {
        int rr = lane + it * 32;
        const __half* base = g_qkv + (size_t)(p0 + rr) * E_QKV + head * 32;
        float qv[32], kv[32], vv[32];
        load32h(qv, base);
        load32h(kv, base + 512);
        load32h(vv, base + 1024);
        #pragma unroll
        for (int d = 0; d < 16; d++) {
            float c = g_cos[rr * 16 + d];
            float s = g_sin[rr * 16 + d];
            float q1 = qv[d], q2 = qv[d + 16];
            qv[d]      = (q1 * c - q2 * s) * scale;
            qv[d + 16] = (q2 * c + q1 * s) * scale;
            float k1 = kv[d], k2 = kv[d + 16];
            kv[d]      = k1 * c - k2 * s;
            kv[d + 16] = k2 * c + k1 * s;
        }
        uint4* qd = (uint4*)(Q + rr * AROW);
        uint4* kd = (uint4*)(K + rr * AROW);
        uint4* vd = (uint4*)(V + rr * AROW);
        #pragma unroll
        for (int i = 0; i < 4; i++) {
            uint4 uq, uk, uv;
            uq.x = packh2(qv[8*i+0], qv[8*i+1]); uq.y = packh2(qv[8*i+2], qv[8*i+3]);
            uq.z = packh2(qv[8*i+4], qv[8*i+5]); uq.w = packh2(qv[8*i+6], qv[8*i+7]);
            uk.x = packh2(kv[8*i+0], kv[8*i+1]); uk.y = packh2(kv[8*i+2], kv[8*i+3]);
            uk.z = packh2(kv[8*i+4], kv[8*i+5]); uk.w = packh2(kv[8*i+6], kv[8*i+7]);
            uv.x = packh2(vv[8*i+0], vv[8*i+1]); uv.y = packh2(vv[8*i+2], vv[8*i+3]);
            uv.z = packh2(vv[8*i+4], vv[8*i+5]); uv.w = packh2(vv[8*i+6], vv[8*i+7]);
            qd[i] = uq; kd[i] = uk; vd[i] = uv;
        }
    }
    __syncwarp();

    const int l7  = lane & 7;
    const int sel = lane >> 3;
    const int a_r = (sel & 1) * 8 + l7;
    const int a_k = (sel >> 1) * 16;
    const int b_r = (sel >> 1) * 8 + l7;
    const int b_k = (sel & 1) * 16;

    // Q fragments: 4 m-tiles x 2 k-tiles
    uint32_t qf[4][2][4];
    #pragma unroll
    for (int mt = 0; mt < 4; mt++)
        #pragma unroll
        for (int kk = 0; kk < 2; kk++)
            ldm_x4(qf[mt][kk], Qs + (mt * 16 + a_r) * AROW + kk * 32 + a_k);

    float oacc[4][4][4];
    #pragma unroll
    for (int i = 0; i < 4; i++)
        #pragma unroll
        for (int j = 0; j < 4; j++)
            #pragma unroll
            for (int q = 0; q < 4; q++) oacc[i][j][q] = 0.f;

    float mrow[4][2], srow[4][2];
    #pragma unroll
    for (int i = 0; i < 4; i++) { mrow[i][0] = mrow[i][1] = -1e30f; srow[i][0] = srow[i][1] = 0.f; }

    #pragma unroll 1
    for (int c0 = 0; c0 < 64; c0 += 16) {
        // K fragments for this 16-key chunk: 2 n-tiles x 2 k-tiles
        uint32_t kf[2][2][2];
        #pragma unroll
        for (int kk = 0; kk < 2; kk++) {
            uint32_t t4[4];
            ldm_x4(t4, Ks + (c0 + b_r) * AROW + kk * 32 + b_k);
            kf[0][kk][0] = t4[0]; kf[0][kk][1] = t4[1];
            kf[1][kk][0] = t4[2]; kf[1][kk][1] = t4[3];
        }

        // S chunk = Q K^T : 4 mt x 2 nt
        float sc[4][2][4];
        #pragma unroll
        for (int mt = 0; mt < 4; mt++)
            #pragma unroll
            for (int nt = 0; nt < 2; nt++) {
                #pragma unroll
                for (int q = 0; q < 4; q++) sc[mt][nt][q] = 0.f;
                mma_f16(sc[mt][nt], qf[mt][0], kf[nt][0]);
                mma_f16(sc[mt][nt], qf[mt][1], kf[nt][1]);
            }

        // softmax statistics + exp + pack P, rescale O
        uint32_t pf[4][4];
        float fr[4][2];
        #pragma unroll
        for (int mt = 0; mt < 4; mt++) {
            #pragma unroll
            for (int h2 = 0; h2 < 2; h2++) {
                float v0 = sc[mt][0][2 * h2], v1 = sc[mt][0][2 * h2 + 1];
                float v2 = sc[mt][1][2 * h2], v3 = sc[mt][1][2 * h2 + 1];
                float cm = fmaxf(fmaxf(v0, v1), fmaxf(v2, v3));
                cm = fmaxf(cm, __shfl_xor_sync(0xFFFFFFFF, cm, 1));
                cm = fmaxf(cm, __shfl_xor_sync(0xFFFFFFFF, cm, 2));
                float mn = fmaxf(mrow[mt][h2], cm);
                float f  = __expf(mrow[mt][h2] - mn);
                mrow[mt][h2] = mn;
                fr[mt][h2]   = f;
                float e0 = __expf(v0 - mn), e1 = __expf(v1 - mn);
                float e2 = __expf(v2 - mn), e3 = __expf(v3 - mn);
                float cs = e0 + e1 + e2 + e3;
                cs += __shfl_xor_sync(0xFFFFFFFF, cs, 1);
                cs += __shfl_xor_sync(0xFFFFFFFF, cs, 2);
                srow[mt][h2] = srow[mt][h2] * f + cs;
                sc[mt][0][2 * h2] = e0; sc[mt][0][2 * h2 + 1] = e1;
                sc[mt][1][2 * h2] = e2; sc[mt][1][2 * h2 + 1] = e3;
            }
            pf[mt][0] = packh2(sc[mt][0][0], sc[mt][0][1]);
            pf[mt][1] = packh2(sc[mt][0][2], sc[mt][0][3]);
            pf[mt][2] = packh2(sc[mt][1][0], sc[mt][1][1]);
            pf[mt][3] = packh2(sc[mt][1][2], sc[mt][1][3]);
        }

        // V fragments (trans): k rows = chunk keys, n = 32 head dims (4 tiles)
        uint32_t vf[4][2];
        #pragma unroll
        for (int nh = 0; nh < 2; nh++) {
            uint32_t t4[4];
            ldm_x4_trans(t4, Vs + (c0 + (sel & 1) * 8 + l7) * AROW
                               + (sel >> 1) * 16 + nh * 32);
            vf[2 * nh][0] = t4[0]; vf[2 * nh][1] = t4[1];
            vf[2 * nh + 1][0] = t4[2]; vf[2 * nh + 1][1] = t4[3];
        }

        // rescale O, then PV accumulate
        #pragma unroll
        for (int mt = 0; mt < 4; mt++)
            #pragma unroll
            for (int nd = 0; nd < 4; nd++) {
                oacc[mt][nd][0] *= fr[mt][0];
                oacc[mt][nd][1] *= fr[mt][0];
                oacc[mt][nd][2] *= fr[mt][1];
                oacc[mt][nd][3] *= fr[mt][1];
            }
        #pragma unroll
        for (int mt = 0; mt < 4; mt++)
            #pragma unroll
            for (int nd = 0; nd < 4; nd++)
                mma_f16(oacc[mt][nd], pf[mt], vf[nd]);
    }

    // normalize + write out fp16 [p][d]
    #pragma unroll
    for (int mt = 0; mt < 4; mt++) {
        float i0 = 1.f / srow[mt][0];
        float i1 = 1.f / srow[mt][1];
        int r0 = mt * 16 + (lane >> 2);
        #pragma unroll
        for (int nd = 0; nd < 4; nd++) {
            int col = nd * 8 + (lane & 3) * 2;
            __half2 h0 = __floats2half2_rn(oacc[mt][nd][0] * i0, oacc[mt][nd][1] * i0);
            __half2 h1 = __floats2half2_rn(oacc[mt][nd][2] * i1, oacc[mt][nd][3] * i1);
            *(__half2*)(g_ah + (size_t)(p0 + r0) * 512 + head * 32 + col)     = h0;
            *(__half2*)(g_ah + (size_t)(p0 + r0 + 8) * 512 + head * 32 + col) = h1;
        }
    }
}

// ---------------------------------------------------------------------------
// Launch
// ---------------------------------------------------------------------------
extern "C" void kernel_launch(void* const* d_in, const int* in_sizes, int n_in,
                              void* d_out, int out_size)
{
    const float* x     = (const float*)d_in[0];
    const float* ln_g  = (const float*)d_in[1];
    const float* ln_b  = (const float*)d_in[2];
    const float* w_qkv = (const float*)d_in[3];
    const float* w_out = (const float*)d_in[4];
    const float* b_out = (const float*)d_in[5];
    float* out = (float*)d_out;

    cudaFuncSetAttribute(gemm_hmma<0>, cudaFuncAttributeMaxDynamicSharedMemorySize, SM_GEMM);
    cudaFuncSetAttribute(gemm_hmma<1>, cudaFuncAttributeMaxDynamicSharedMemorySize, SM_GEMM);
    cudaFuncSetAttribute(attn_kernel, cudaFuncAttributeMaxDynamicSharedMemorySize, SM_ATT);

    __half *qkv, *xh, *ah, *wq, *wo;
    cudaGetSymbolAddress((void**)&qkv, g_qkv);
    cudaGetSymbolAddress((void**)&xh,  g_xh);
    cudaGetSymbolAddress((void**)&ah,  g_ah);
    cudaGetSymbolAddress((void**)&wq,  g_wq);
    cudaGetSymbolAddress((void**)&wo,  g_wo);

    rope_init_kernel<<<1, 512>>>();
    convw_kernel<<<(E_QKV * KDIM + 255) / 256, 256>>>(w_qkv, wq, E_QKV * KDIM);
    convw_kernel<<<(KDIM * KDIM + 255) / 256, 256>>>(w_out, wo, KDIM * KDIM);
    ln_window_kernel<<<2048, 256>>>(x, ln_g, ln_b);

    {
        dim3 grid(E_QKV / 128, P_TOT / 128);   // (12, 512), bm fastest for L2 reuse
        gemm_hmma<0><<<grid, 256, SM_GEMM>>>(wq, xh, qkv, nullptr, E_QKV);
    }

    {
        dim3 grid(NWIN, HEADS / 4);            // (1024, 4), 4 warps = 4 heads/block
        attn_kernel<<<grid, 128, SM_ATT>>>();
    }

    {
        dim3 grid(KDIM / 128, P_TOT / 128);    // (4, 512)
        gemm_hmma<1><<<grid, 256, SM_GEMM>>>(wo, ah, out, b_out, 0);
    }
}